// round 4
// baseline (speedup 1.0000x reference)
#include <cuda_runtime.h>
#include <cuda_bf16.h>

#define KDIM 64
#define MAXB 1024
#define PF   4   // prefetch depth (steps)

__device__ float g_partial[MAXB];

typedef unsigned long long ull;

__device__ __forceinline__ void fma2(ull& acc, ull a, ull b) {
    asm("fma.rn.f32x2 %0, %1, %2, %3;" : "=l"(acc) : "l"(a), "l"(b), "l"(acc));
}
__device__ __forceinline__ void add2(ull& d, ull a, ull b) {
    asm("add.rn.f32x2 %0, %1, %2;" : "=l"(d) : "l"(a), "l"(b));
}

// One block per batch; thread j owns CRF state column j.
// LINEAR-space recursion with exact power-of-2 renormalization:
//   a_hat[t+1][j] = ( sum_i a_hat[t][i] * E[i][j] ) * P[t][j] * 2^{-(e-127)}
// where E = exp(trans) (registers), P = exp(emit) (precomputed at refill),
// e = exponent bits of a_hat[t][0] (spread of alpha is bounded, so any
// single element is a valid scale pivot). Stot accumulates the exponents;
// log happens exactly once at the end. NO MUFU and NO global load on the
// per-step critical chain; gold-score transition values are broadcast-LDG'd
// PF steps ahead in the refill stage.
__global__ __launch_bounds__(64, 8)
void crf_forward_kernel(const float* __restrict__ emis,
                        const float* __restrict__ trans,
                        const float* __restrict__ start_t,
                        const float* __restrict__ end_t,
                        const int*  __restrict__ labels,
                        const int*  __restrict__ sent_len,
                        int T)
{
    const int b = blockIdx.x;
    const int j = threadIdx.x;
    const int L = sent_len[b];
    const float* em  = emis   + (size_t)b * T * KDIM;
    const int*   lab = labels + (size_t)b * T;

    __shared__ __align__(16) float sa[2][KDIM];
    __shared__ float rsum[2], rgold[2];

    // E column j as 32 packed (even,odd) f32x2 pairs -> 64 regs
    ull Epk[KDIM / 2];
#pragma unroll
    for (int i2 = 0; i2 < KDIM / 2; ++i2) {
        const float lo = __expf(trans[(2 * i2)     * KDIM + j]);
        const float hi = __expf(trans[(2 * i2 + 1) * KDIM + j]);
        Epk[i2] = (ull)__float_as_uint(lo) | ((ull)__float_as_uint(hi) << 32);
    }

    // t = 0 (alpha0 in log space ~ +-12, exp is safe in fp32)
    const float a0log = start_t[j] + em[j];
    float a = __expf(a0log);
    int   Stot = 0;
    float gold_emit  = 0.0f;   // per-thread masked (emission + start/end terms)
    float gold_trans = 0.0f;   // uniform across threads (broadcast tv)
    int   lab_last = lab[0];
    if (j == lab_last) gold_emit = a0log;

    // prefetch rings for steps t = 1..PF :
    //   er = raw emission (gold), Pr = exp(emission), lb = label,
    //   tv = trans[lab[t-1]][lab[t]] (broadcast)
    float er[PF], Pr[PF], tv[PF];
    int   lb[PF];
#pragma unroll
    for (int k = 0; k < PF; ++k) {
        int tt = 1 + k; if (tt > T - 1) tt = T - 1;
        const float ee = em[(size_t)tt * KDIM + j];
        er[k] = ee;
        Pr[k] = __expf(ee);
        const int l1 = lab[tt];
        lb[k] = l1;
        tv[k] = trans[lab[tt - 1] * KDIM + l1];
    }

    int buf = 0;
    auto step = [&](float P, float eraw, int labt, float tvv) {
        sa[buf][j] = a;
        __syncthreads();
        // gold terms: all operands already in registers (no memory on chain)
        if (j == labt) gold_emit += eraw;
        gold_trans += tvv;                 // uniform; counted once at the end
        lab_last = labt;
        // renorm scale from pivot element's exponent (exact power of 2)
        const float s0 = sa[buf][0];       // broadcast LDS
        const int   e  = (int)((__float_as_uint(s0) >> 23) & 0xffu);
        const float scl = __uint_as_float((unsigned)(254 - e) << 23); // 2^(127-e)
        Stot += e - 127;
        // dot_j = sum_i sa[i] * E[i][j]
        ull a0 = 0ull, a1 = 0ull, a2 = 0ull, a3 = 0ull;
        const ulonglong2* sv = (const ulonglong2*)sa[buf];
#pragma unroll
        for (int q = 0; q < 8; ++q) {
            const ulonglong2 v0 = sv[2 * q];
            const ulonglong2 v1 = sv[2 * q + 1];
            fma2(a0, v0.x, Epk[4 * q + 0]);
            fma2(a1, v0.y, Epk[4 * q + 1]);
            fma2(a2, v1.x, Epk[4 * q + 2]);
            fma2(a3, v1.y, Epk[4 * q + 3]);
        }
        add2(a0, a0, a1);
        add2(a2, a2, a3);
        add2(a0, a0, a2);
        const float dot = __uint_as_float((unsigned)a0)
                        + __uint_as_float((unsigned)(a0 >> 32));
        a = dot * scl * P;
        buf ^= 1;
    };

    int t = 1;
    for (; t + PF <= L; t += PF) {
#pragma unroll
        for (int k = 0; k < PF; ++k) {
            const float Pc = Pr[k], ec = er[k], tc = tv[k];
            const int   lc = lb[k];
            int tp = t + PF + k; if (tp > T - 1) tp = T - 1;
            const float ee = em[(size_t)tp * KDIM + j];   // deep prefetch
            er[k] = ee;
            Pr[k] = __expf(ee);
            const int l1 = lab[tp];
            lb[k] = l1;
            tv[k] = trans[lab[tp - 1] * KDIM + l1];
            step(Pc, ec, lc, tc);
        }
    }
    for (int k = 0; t < L; ++t, ++k) {     // tail: ring already filled
        step(Pr[k], er[k], lb[k], tv[k]);
    }

    // gold end term
    if (j == lab_last) gold_emit += end_t[j];

    // fwd = log( sum_j a[j]*exp(end[j]) ) + Stot*ln2
    const float x = a * __expf(end_t[j]);
    float xs = x;
    float gg = gold_emit;
#pragma unroll
    for (int o = 16; o; o >>= 1) {
        xs += __shfl_xor_sync(0xffffffffu, xs, o);
        gg += __shfl_xor_sync(0xffffffffu, gg, o);
    }
    if ((j & 31) == 0) { rsum[j >> 5] = xs; rgold[j >> 5] = gg; }
    __syncthreads();

    if (j == 0) {
        const float fwd = __logf(rsum[0] + rsum[1])
                        + (float)Stot * 0.69314718055994530942f;
        g_partial[b] = fwd - (rgold[0] + rgold[1] + gold_trans);
    }
}

// Deterministic final reduction: out = sum(partial)/B
__global__ void crf_reduce_kernel(float* __restrict__ out, int B)
{
    __shared__ float ws[16];
    const int tid = threadIdx.x;
    float v = 0.0f;
    for (int i = tid; i < B; i += blockDim.x) v += g_partial[i];
#pragma unroll
    for (int o = 16; o; o >>= 1) v += __shfl_xor_sync(0xffffffffu, v, o);
    if ((tid & 31) == 0) ws[tid >> 5] = v;
    __syncthreads();
    if (tid < 16) {
        float u = (tid < (blockDim.x + 31) / 32) ? ws[tid] : 0.0f;
#pragma unroll
        for (int o = 8; o; o >>= 1) u += __shfl_xor_sync(0x0000ffffu, u, o);
        if (tid == 0) out[0] = u / (float)B;
    }
}

extern "C" void kernel_launch(void* const* d_in, const int* in_sizes, int n_in,
                              void* d_out, int out_size)
{
    const float* emis    = (const float*)d_in[0];
    const float* trans   = (const float*)d_in[1];
    const float* start_t = (const float*)d_in[2];
    const float* end_t   = (const float*)d_in[3];
    const int*   labels  = (const int*)d_in[4];
    const int*   slen    = (const int*)d_in[5];

    const int B = in_sizes[5];            // 512
    const int T = in_sizes[4] / B;        // 1024
    float* out = (float*)d_out;

    crf_forward_kernel<<<B, KDIM>>>(emis, trans, start_t, end_t, labels, slen, T);
    crf_reduce_kernel<<<1, 512>>>(out, B);
}

// round 5
// speedup vs baseline: 1.2433x; 1.2433x over previous
#include <cuda_runtime.h>
#include <cuda_bf16.h>

#define KDIM 64
#define MAXB 1024
#define PF   4   // prefetch depth (steps)

__device__ float g_partial[MAXB];

typedef unsigned long long ull;

__device__ __forceinline__ void fma2(ull& acc, ull a, ull b) {
    asm("fma.rn.f32x2 %0, %1, %2, %3;" : "=l"(acc) : "l"(a), "l"(b), "l"(acc));
}
__device__ __forceinline__ void add2(ull& d, ull a, ull b) {
    asm("add.rn.f32x2 %0, %1, %2;" : "=l"(d) : "l"(a), "l"(b));
}

// ONE WARP PER BATCH. Lane l owns columns j0=2l, j1=2l+1.
// Linear-space recursion with exact power-of-2 renorm (validated in R4):
//   a[t+1][j] = ( sum_i a[t][i] * E[i][j] ) * 2^(127-e) * exp(emit[t][j])
// E = exp(trans) in registers (64 packed f32x2 pairs -> 128 regs).
// No __syncthreads: single STS.64 + __syncwarp + 16 broadcast LDS.128 per step.
// All global traffic (emissions, labels, gold transition values) prefetched
// PF steps ahead; renorm pivot via shfl of lane 0 (off the critical chain).
__global__ __launch_bounds__(32, 1)
void crf_forward_kernel(const float* __restrict__ emis,
                        const float* __restrict__ trans,
                        const float* __restrict__ start_t,
                        const float* __restrict__ end_t,
                        const int*  __restrict__ labels,
                        const int*  __restrict__ sent_len,
                        int T)
{
    const int b    = blockIdx.x;
    const int lane = threadIdx.x;
    const int j0   = 2 * lane;
    const int j1   = j0 + 1;
    const int L    = sent_len[b];
    const float* em  = emis   + (size_t)b * T * KDIM;
    const int*   lab = labels + (size_t)b * T;

    __shared__ __align__(16) float sa[2][KDIM];

    // E pairs over i for the two owned columns: 64 ull = 128 regs
    ull Epk0[KDIM / 2], Epk1[KDIM / 2];
#pragma unroll
    for (int i2 = 0; i2 < KDIM / 2; ++i2) {
        const float a00 = __expf(trans[(2 * i2)     * KDIM + j0]);
        const float a10 = __expf(trans[(2 * i2 + 1) * KDIM + j0]);
        const float a01 = __expf(trans[(2 * i2)     * KDIM + j1]);
        const float a11 = __expf(trans[(2 * i2 + 1) * KDIM + j1]);
        Epk0[i2] = (ull)__float_as_uint(a00) | ((ull)__float_as_uint(a10) << 32);
        Epk1[i2] = (ull)__float_as_uint(a01) | ((ull)__float_as_uint(a11) << 32);
    }

    // t = 0
    const float2 st  = ((const float2*)start_t)[lane];
    const float2 em0 = ((const float2*)em)[lane];
    const float l0x = st.x + em0.x;
    const float l0y = st.y + em0.y;
    float ax = __expf(l0x);
    float ay = __expf(l0y);
    int   Stot = 0;
    float gold_emit  = 0.0f;   // per-lane masked emission (+start/end) terms
    float gold_trans = 0.0f;   // uniform across lanes (broadcast tv)
    int   lab_last = lab[0];
    if (j0 == lab_last) gold_emit = l0x;
    if (j1 == lab_last) gold_emit = l0y;

    // prefetch rings for steps t = 1..PF
    float2 er[PF], Pr[PF];
    float  tvr[PF];
    int    lbr[PF];
    int lab_roll = lab_last;                  // lab[t-1] rolling value
#pragma unroll
    for (int k = 0; k < PF; ++k) {
        int tt = 1 + k; if (tt > T - 1) tt = T - 1;
        const float2 ee = ((const float2*)(em + (size_t)tt * KDIM))[lane];
        er[k] = ee;
        Pr[k] = make_float2(__expf(ee.x), __expf(ee.y));
        const int l1 = lab[tt];
        lbr[k] = l1;
        tvr[k] = trans[lab_roll * KDIM + l1];
        lab_roll = l1;
    }

    int buf = 0;
    auto step = [&](float2 P, float2 eraw, int labt, float tvv) {
        // pivot from lane 0's register (off-chain)
        const float piv = __shfl_sync(0xffffffffu, ax, 0);
        ((float2*)sa[buf])[lane] = make_float2(ax, ay);
        __syncwarp();
        const int   e   = (int)((__float_as_uint(piv) >> 23) & 0xffu);
        const float scl = __uint_as_float((unsigned)(254 - e) << 23); // 2^(127-e)
        Stot += e - 127;
        // gold terms (all in registers)
        if (j0 == labt) gold_emit += eraw.x;
        if (j1 == labt) gold_emit += eraw.y;
        gold_trans += tvv;
        lab_last = labt;
        // two dots (columns j0, j1) sharing the sa loads
        ull b0 = 0ull, b1 = 0ull, b2 = 0ull, b3 = 0ull;
        ull c0 = 0ull, c1 = 0ull, c2 = 0ull, c3 = 0ull;
        const ulonglong2* sv = (const ulonglong2*)sa[buf];
#pragma unroll
        for (int q = 0; q < 8; ++q) {
            const ulonglong2 v0 = sv[2 * q];
            const ulonglong2 v1 = sv[2 * q + 1];
            fma2(b0, v0.x, Epk0[4 * q + 0]);  fma2(c0, v0.x, Epk1[4 * q + 0]);
            fma2(b1, v0.y, Epk0[4 * q + 1]);  fma2(c1, v0.y, Epk1[4 * q + 1]);
            fma2(b2, v1.x, Epk0[4 * q + 2]);  fma2(c2, v1.x, Epk1[4 * q + 2]);
            fma2(b3, v1.y, Epk0[4 * q + 3]);  fma2(c3, v1.y, Epk1[4 * q + 3]);
        }
        add2(b0, b0, b1); add2(b2, b2, b3); add2(b0, b0, b2);
        add2(c0, c0, c1); add2(c2, c2, c3); add2(c0, c0, c2);
        const float d0 = __uint_as_float((unsigned)b0)
                       + __uint_as_float((unsigned)(b0 >> 32));
        const float d1 = __uint_as_float((unsigned)c0)
                       + __uint_as_float((unsigned)(c0 >> 32));
        ax = d0 * scl * P.x;
        ay = d1 * scl * P.y;
        buf ^= 1;
    };

    int t = 1;
    for (; t + PF <= L; t += PF) {
#pragma unroll
        for (int k = 0; k < PF; ++k) {
            const float2 Pc = Pr[k], ec = er[k];
            const float  tc = tvr[k];
            const int    lc = lbr[k];
            int tp = t + PF + k; if (tp > T - 1) tp = T - 1;
            const float2 ee = ((const float2*)(em + (size_t)tp * KDIM))[lane];
            er[k] = ee;
            Pr[k] = make_float2(__expf(ee.x), __expf(ee.y));
            const int l1 = lab[tp];
            lbr[k] = l1;
            tvr[k] = trans[lab_roll * KDIM + l1];   // value garbage if clamped; never consumed
            lab_roll = l1;
            step(Pc, ec, lc, tc);
        }
    }
    for (int k = 0; t < L; ++t, ++k) {     // tail: ring already filled
        step(Pr[k], er[k], lbr[k], tvr[k]);
    }

    // gold end term
    {
        const float2 en = ((const float2*)end_t)[lane];
        if (j0 == lab_last) gold_emit += en.x;
        if (j1 == lab_last) gold_emit += en.y;
        // fwd = log( sum_j a[j]*exp(end[j]) ) + Stot*ln2
        float xs = ax * __expf(en.x) + ay * __expf(en.y);
        float gg = gold_emit;
#pragma unroll
        for (int o = 16; o; o >>= 1) {
            xs += __shfl_xor_sync(0xffffffffu, xs, o);
            gg += __shfl_xor_sync(0xffffffffu, gg, o);
        }
        if (lane == 0) {
            const float fwd = __logf(xs) + (float)Stot * 0.69314718055994530942f;
            g_partial[b] = fwd - (gg + gold_trans);
        }
    }
}

// Deterministic final reduction: out = sum(partial)/B
__global__ void crf_reduce_kernel(float* __restrict__ out, int B)
{
    __shared__ float ws[16];
    const int tid = threadIdx.x;
    float v = 0.0f;
    for (int i = tid; i < B; i += blockDim.x) v += g_partial[i];
#pragma unroll
    for (int o = 16; o; o >>= 1) v += __shfl_xor_sync(0xffffffffu, v, o);
    if ((tid & 31) == 0) ws[tid >> 5] = v;
    __syncthreads();
    if (tid < 16) {
        float u = (tid < (blockDim.x + 31) / 32) ? ws[tid] : 0.0f;
#pragma unroll
        for (int o = 8; o; o >>= 1) u += __shfl_xor_sync(0x0000ffffu, u, o);
        if (tid == 0) out[0] = u / (float)B;
    }
}

extern "C" void kernel_launch(void* const* d_in, const int* in_sizes, int n_in,
                              void* d_out, int out_size)
{
    const float* emis    = (const float*)d_in[0];
    const float* trans   = (const float*)d_in[1];
    const float* start_t = (const float*)d_in[2];
    const float* end_t   = (const float*)d_in[3];
    const int*   labels  = (const int*)d_in[4];
    const int*   slen    = (const int*)d_in[5];

    const int B = in_sizes[5];            // 512
    const int T = in_sizes[4] / B;        // 1024
    float* out = (float*)d_out;

    crf_forward_kernel<<<B, 32>>>(emis, trans, start_t, end_t, labels, slen, T);
    crf_reduce_kernel<<<1, 512>>>(out, B);
}